// round 15
// baseline (speedup 1.0000x reference)
#include <cuda_runtime.h>
#include <cuda_bf16.h>
#include <cuda_fp16.h>
#include <stdint.h>
#include <math.h>

#define N_NODES 50000
#define N_PAD   50048   // padded row count for OOB-safe cp.async
#define N_FEAT  256
#define HC      256     // N_HEADS * N_HID
#define NH      8
#define NC      32      // classes
#define N_EDGES 800000
#define TOT_E   (N_EDGES + N_NODES)   // 850000
#define SCAN_B  1024
#define NBLK    ((N_NODES + SCAN_B - 1) / SCAN_B)   // 49

// ---------------- scratch (__device__ globals; no runtime allocation) -------
__device__ __align__(16) __half g_xh[(size_t)N_PAD * N_FEAT];  // 25.6 MB x fp16
__device__ __align__(16) __half g_z1h[(size_t)N_NODES * HC];   // 25.6 MB
__device__ __align__(16) __half g_h1h[(size_t)N_PAD * HC];     // 25.6 MB h1 fp16
__device__ __align__(16) float g_as1[N_NODES * NH];
__device__ __align__(16) float g_ad1[N_NODES * NH];
__device__ __align__(16) __half g_z2h[(size_t)N_NODES * NC];   // 3.2 MB
__device__            float g_as2[N_NODES];
__device__            float g_ad2[N_NODES];
__device__            int   g_src[TOT_E];
__device__            int   g_dst[TOT_E];
__device__            int   g_deg[N_NODES];
__device__            int   g_rowptr[N_NODES + 1];
__device__            int   g_wp[N_NODES];
__device__            int   g_csrc[TOT_E];
__device__            int   g_bsum[NBLK];
__device__            int   g_is64;
__device__ __align__(16) __half g_w1h[N_FEAT * HC];  // [N=256][K=256] fp16 hi
__device__ __align__(16) __half g_w1l[N_FEAT * HC];  // fp16 lo (residual)
__device__ __align__(16) __half g_w2h[NC * N_FEAT];  // [N=32][K=256]
__device__ __align__(16) __half g_w2l[NC * N_FEAT];

// ---------------- helpers ---------------------------------------------------
__device__ __forceinline__ float lrelu(float x) { return x > 0.f ? x : 0.2f * x; }

__device__ __forceinline__ unsigned int pack_h2(float a, float b) {
    __half2 p = __floats2half2_rn(a, b);
    return *reinterpret_cast<unsigned int*>(&p);
}
__device__ __forceinline__ uint32_t smem_u32(const void* p) {
    uint32_t a;
    asm("{ .reg .u64 t; cvta.to.shared.u64 t, %1; cvt.u32.u64 %0, t; }"
        : "=r"(a) : "l"(p));
    return a;
}
__device__ __forceinline__ void cp16(uint32_t s, const void* g) {
    asm volatile("cp.async.cg.shared.global [%0], [%1], 16;" :: "r"(s), "l"(g));
}
__device__ __forceinline__ void cp_commit() {
    asm volatile("cp.async.commit_group;");
}
__device__ __forceinline__ void cp_wait0() {
    asm volatile("cp.async.wait_group 0;" ::: "memory");
}
__device__ __forceinline__ void ldsm_x4(uint32_t& r0, uint32_t& r1,
                                        uint32_t& r2, uint32_t& r3, uint32_t addr) {
    asm volatile("ldmatrix.sync.aligned.m8n8.x4.shared.b16 {%0,%1,%2,%3}, [%4];"
                 : "=r"(r0), "=r"(r1), "=r"(r2), "=r"(r3) : "r"(addr));
}
__device__ __forceinline__ void ldsm_x2(uint32_t& r0, uint32_t& r1, uint32_t addr) {
    asm volatile("ldmatrix.sync.aligned.m8n8.x2.shared.b16 {%0,%1}, [%2];"
                 : "=r"(r0), "=r"(r1) : "r"(addr));
}
// f16 MMA: D(f32) += A(f16) x B(f16)
__device__ __forceinline__ void mma16816h(float* c, const uint32_t* a, const uint32_t* b) {
    asm volatile(
        "mma.sync.aligned.m16n8k16.row.col.f32.f16.f16.f32 "
        "{%0,%1,%2,%3}, {%4,%5,%6,%7}, {%8,%9}, {%0,%1,%2,%3};"
        : "+f"(c[0]), "+f"(c[1]), "+f"(c[2]), "+f"(c[3])
        : "r"(a[0]), "r"(a[1]), "r"(a[2]), "r"(a[3]), "r"(b[0]), "r"(b[1]));
}
// swizzled byte offset in a [rows][32] 16-bit tile (64B rows, chunk-XOR)
__device__ __forceinline__ uint32_t swz(int r, int k) {
    return (uint32_t)(r * 64 + ((((k >> 3) ^ ((r >> 1) & 3)) << 4) | ((k & 7) << 1)));
}

// ---------------- prep: edge-dtype detect + deg zero + W fp16 hi/lo splits ---
__global__ void prep_kernel(const float* __restrict__ W1,
                            const float* __restrict__ W2,
                            const void* __restrict__ ei) {
    int idx = blockIdx.x * blockDim.x + threadIdx.x;
    if (idx == 0) {
        const long long* e64 = (const long long*)ei;
        int ok = 1;
        for (int i = 0; i < 64; i++) {
            long long v = e64[i];
            if (v < 0 || v >= N_NODES) { ok = 0; break; }
        }
        g_is64 = ok;
    }
    if (idx < N_FEAT * HC) {
        int n = idx >> 8, k = idx & 255;
        float w = W1[k * HC + n];
        __half h = __float2half_rn(w);
        g_w1h[n * N_FEAT + k] = h;
        g_w1l[n * N_FEAT + k] = __float2half_rn(w - __half2float(h));
    }
    if (idx < NC * N_FEAT) {
        int n = idx >> 8, k = idx & 255;
        float w = W2[k * NC + n];
        __half h = __float2half_rn(w);
        g_w2h[n * N_FEAT + k] = h;
        g_w2l[n * N_FEAT + k] = __float2half_rn(w - __half2float(h));
    }
    if (idx < N_NODES) g_deg[idx] = 0;
}

// ---------------- xprep: x fp32 -> fp16 (one 8-elem chunk per thread) --------
__global__ void xprep_kernel(const float* __restrict__ x) {
    size_t i = (size_t)blockIdx.x * blockDim.x + threadIdx.x;
    size_t base = i * 8;
    if (base >= (size_t)N_NODES * N_FEAT) return;
    float4 v0 = *(const float4*)(x + base);
    float4 v1 = *(const float4*)(x + base + 4);
    uint4 hv = make_uint4(pack_h2(v0.x, v0.y), pack_h2(v0.z, v0.w),
                          pack_h2(v1.x, v1.y), pack_h2(v1.z, v1.w));
    *(uint4*)(g_xh + base) = hv;
}

__global__ void decode_kernel(const void* __restrict__ ei) {
    int e = blockIdx.x * blockDim.x + threadIdx.x;
    if (e >= TOT_E) return;
    int src, dst;
    if (e >= N_EDGES) {
        src = dst = e - N_EDGES;           // self loop
    } else if (g_is64) {
        const long long* p = (const long long*)ei;
        src = (int)p[e]; dst = (int)p[N_EDGES + e];
    } else {
        const int* p = (const int*)ei;
        src = p[e]; dst = p[N_EDGES + e];
    }
    g_src[e] = src;
    g_dst[e] = dst;
    atomicAdd(&g_deg[dst], 1);
}

// ---------------- multi-block exclusive scan of g_deg ------------------------
__global__ __launch_bounds__(SCAN_B) void scan1_kernel() {
    __shared__ int warp_sums[32];
    int tid = threadIdx.x, lane = tid & 31, wid = tid >> 5;
    int i = blockIdx.x * SCAN_B + tid;
    int v = (i < N_NODES) ? g_deg[i] : 0;
    int x = v;
#pragma unroll
    for (int o = 1; o < 32; o <<= 1) {
        int y = __shfl_up_sync(0xFFFFFFFFu, x, o);
        if (lane >= o) x += y;
    }
    if (lane == 31) warp_sums[wid] = x;
    __syncthreads();
    if (wid == 0) {
        int s = warp_sums[lane];
#pragma unroll
        for (int o = 1; o < 32; o <<= 1) {
            int y = __shfl_up_sync(0xFFFFFFFFu, s, o);
            if (lane >= o) s += y;
        }
        warp_sums[lane] = s;
    }
    __syncthreads();
    int excl = x - v + (wid > 0 ? warp_sums[wid - 1] : 0);
    if (i < N_NODES) g_rowptr[i] = excl;
    if (tid == SCAN_B - 1) g_bsum[blockIdx.x] = excl + v;
}

__global__ void scan2_kernel() {
    int run = 0;
    for (int b = 0; b < NBLK; b++) {
        int t = g_bsum[b];
        g_bsum[b] = run;
        run += t;
    }
}

__global__ __launch_bounds__(SCAN_B) void scan3_kernel() {
    int i = blockIdx.x * SCAN_B + threadIdx.x;
    if (i < N_NODES) {
        int r = g_rowptr[i] + g_bsum[blockIdx.x];
        g_rowptr[i] = r;
        g_wp[i] = r;
    }
    if (i == 0) g_rowptr[N_NODES] = TOT_E;
}

__global__ void scatter_kernel() {
    int e = blockIdx.x * blockDim.x + threadIdx.x;
    if (e >= TOT_E) return;
    int pos = atomicAdd(&g_wp[g_dst[e]], 1);
    g_csrc[pos] = g_src[e];
}

// ---------------- mma.sync GEMM1: z1 = xh @ W1, fp16 A + split-fp16 B --------
// CTA: 256 thr (8 warps), tile 128(M) x 128(N); warp tile 64x32 (one head).
// All operands staged via cp.async (A pre-converted fp16). Double-buffered.
// Buffer layout (24K each): A 8K | BH 8K | BL 8K. Total smem 48K.
#define MG1_BUF 24576
__global__ __launch_bounds__(256, 2) void mmagemm1(const float* __restrict__ a_src,
                                                   const float* __restrict__ a_dst) {
    extern __shared__ char sm1[];
    uint32_t base = smem_u32(sm1);

    int tid  = threadIdx.x, lane = tid & 31, wid = tid >> 5;
    int bcol = blockIdx.x;                  // 0,1 -> n half
    int row0 = blockIdx.y * 128;
    int mwarp = wid >> 2, nwarp = wid & 3;  // 2 x 4 warp grid
    int n0 = bcol * 128;

    // per-thread staging coordinates (2 chunks of 8 fp16 = 16B)
    int r0s = tid >> 2,          c0s = (tid & 3) << 3;
    int r1s = (tid + 256) >> 2,  c1s = (tid & 3) << 3;
    uint32_t swA0 = swz(r0s, c0s), swA1 = swz(r1s, c1s);

    float C[4][4][4];
#pragma unroll
    for (int mt = 0; mt < 4; mt++)
#pragma unroll
        for (int nt = 0; nt < 4; nt++)
#pragma unroll
            for (int j = 0; j < 4; j++) C[mt][nt][j] = 0.f;

    auto issueAB = [&](int kt, uint32_t bufoff) {
#pragma unroll
        for (int i = 0; i < 2; i++) {
            int r = i ? r1s : r0s, c = i ? c1s : c0s;
            uint32_t so = i ? swA1 : swA0;
            cp16(base + bufoff + so,
                 g_xh + (size_t)(row0 + r) * N_FEAT + kt * 32 + c);
            cp16(base + bufoff + 8192 + so,
                 g_w1h + (size_t)(n0 + r) * N_FEAT + kt * 32 + c);
            cp16(base + bufoff + 16384 + so,
                 g_w1l + (size_t)(n0 + r) * N_FEAT + kt * 32 + c);
        }
    };

    // prologue: fill buffer 0
    issueAB(0, 0);
    cp_commit();
    cp_wait0();
    __syncthreads();

    for (int kt = 0; kt < 8; kt++) {
        uint32_t cur = (uint32_t)(kt & 1) * MG1_BUF;
        uint32_t nxt = MG1_BUF - cur;
        if (kt < 7) {
            issueAB(kt + 1, nxt);
            cp_commit();
        }
        uint32_t uA = base + cur;
        uint32_t uBh = uA + 8192, uBl = uA + 16384;

#pragma unroll
        for (int ki = 0; ki < 2; ki++) {
            uint32_t Ah[4][4], Bh[4][2], Bl[4][2];
            int g = lane >> 3, lr = lane & 7;
            int arow = mwarp * 64 + (g & 1) * 8 + lr;
            int ak = ki * 16 + (g >> 1) * 8;
#pragma unroll
            for (int mt = 0; mt < 4; mt++) {
                uint32_t so = swz(arow + mt * 16, ak);
                ldsm_x4(Ah[mt][0], Ah[mt][1], Ah[mt][2], Ah[mt][3], uA + so);
            }
            int bn = nwarp * 32 + (lane & 7);
            int bk = ki * 16 + ((lane >> 3) & 1) * 8;
#pragma unroll
            for (int nt = 0; nt < 4; nt++) {
                uint32_t so = swz(bn + nt * 8, bk);
                ldsm_x2(Bh[nt][0], Bh[nt][1], uBh + so);
                ldsm_x2(Bl[nt][0], Bl[nt][1], uBl + so);
            }
#pragma unroll
            for (int mt = 0; mt < 4; mt++)
#pragma unroll
                for (int nt = 0; nt < 4; nt++) {
                    mma16816h(C[mt][nt], Ah[mt], Bh[nt]);
                    mma16816h(C[mt][nt], Ah[mt], Bl[nt]);
                }
        }
        if (kt < 7) cp_wait0();
        __syncthreads();
    }

    // ---- epilogue: z1(fp16) stores + fused alpha1 dots (warp cols = 1 head) -
    int q = lane & 3, hrow = lane >> 2;
    int head = bcol * 4 + nwarp;
    float asr[8], adr[8];
#pragma unroll
    for (int nt = 0; nt < 4; nt++)
#pragma unroll
        for (int j = 0; j < 2; j++) {
            int col = head * 32 + nt * 8 + q * 2 + j;
            asr[nt * 2 + j] = __ldg(a_src + col);
            adr[nt * 2 + j] = __ldg(a_dst + col);
        }

#pragma unroll
    for (int mt = 0; mt < 4; mt++) {
        int ra = row0 + mwarp * 64 + mt * 16 + hrow;
        int rb = ra + 8;
        float sa = 0.f, da = 0.f, sb2 = 0.f, db = 0.f;
#pragma unroll
        for (int nt = 0; nt < 4; nt++) {
            sa  += C[mt][nt][0] * asr[nt * 2] + C[mt][nt][1] * asr[nt * 2 + 1];
            da  += C[mt][nt][0] * adr[nt * 2] + C[mt][nt][1] * adr[nt * 2 + 1];
            sb2 += C[mt][nt][2] * asr[nt * 2] + C[mt][nt][3] * asr[nt * 2 + 1];
            db  += C[mt][nt][2] * adr[nt * 2] + C[mt][nt][3] * adr[nt * 2 + 1];
        }
#pragma unroll
        for (int o = 1; o <= 2; o <<= 1) {
            sa  += __shfl_xor_sync(0xFFFFFFFFu, sa, o);
            da  += __shfl_xor_sync(0xFFFFFFFFu, da, o);
            sb2 += __shfl_xor_sync(0xFFFFFFFFu, sb2, o);
            db  += __shfl_xor_sync(0xFFFFFFFFu, db, o);
        }
        if (q == 0 && ra < N_NODES) { g_as1[ra * NH + head] = sa;  g_ad1[ra * NH + head] = da; }
        if (q == 0 && rb < N_NODES) { g_as1[rb * NH + head] = sb2; g_ad1[rb * NH + head] = db; }

#pragma unroll
        for (int nt = 0; nt < 4; nt++) {
            int col = head * 32 + nt * 8 + q * 2;
            if (ra < N_NODES)
                *(__half2*)(g_z1h + (size_t)ra * HC + col) =
                    __floats2half2_rn(C[mt][nt][0], C[mt][nt][1]);
            if (rb < N_NODES)
                *(__half2*)(g_z1h + (size_t)rb * HC + col) =
                    __floats2half2_rn(C[mt][nt][2], C[mt][nt][3]);
        }
    }
}

// ---------------- fused layer-1 GAT: softmax + aggregate + bias + ELU --------
// h1 stored directly as fp16 (identical rounding point to the old
// fp32-store + mmagemm2-convert path; zero accuracy change).
__global__ __launch_bounds__(256) void gat1_fused(const float* __restrict__ b1) {
    int lane = threadIdx.x & 31;
    int dst  = blockIdx.x * 8 + (threadIdx.x >> 5);
    if (dst >= N_NODES) return;
    int beg = g_rowptr[dst], end = g_rowptr[dst + 1];

    float ad[NH];
    {
        float4 d0 = *(const float4*)(g_ad1 + dst * NH);
        float4 d1 = *(const float4*)(g_ad1 + dst * NH + 4);
        ad[0]=d0.x; ad[1]=d0.y; ad[2]=d0.z; ad[3]=d0.w;
        ad[4]=d1.x; ad[5]=d1.y; ad[6]=d1.z; ad[7]=d1.w;
    }

    float sm[NH];
#pragma unroll
    for (int h = 0; h < NH; h++) sm[h] = 0.f;
    for (int j = beg + lane; j < end; j += 32) {
        int s = g_csrc[j];
        float4 s0 = *(const float4*)(g_as1 + s * NH);
        float4 s1 = *(const float4*)(g_as1 + s * NH + 4);
        float as[NH] = {s0.x, s0.y, s0.z, s0.w, s1.x, s1.y, s1.z, s1.w};
#pragma unroll
        for (int h = 0; h < NH; h++)
            sm[h] += __expf(lrelu(as[h] + ad[h]));
    }
#pragma unroll
    for (int h = 0; h < NH; h++)
#pragma unroll
        for (int o = 16; o; o >>= 1)
            sm[h] += __shfl_xor_sync(0xFFFFFFFFu, sm[h], o);

    int   hme  = lane >> 2;
    float invm = 1.f / sm[hme];
    float adm  = ad[hme];

    float acc[8];
#pragma unroll
    for (int i = 0; i < 8; i++) acc[i] = 0.f;
#pragma unroll 8
    for (int j = beg; j < end; j++) {
        int s = g_csrc[j];
        float wt = __expf(lrelu(g_as1[s * NH + hme] + adm)) * invm;
        uint4 zv = *((const uint4*)(g_z1h + (size_t)s * HC) + lane);
        float2 p0 = __half22float2(*(__half2*)&zv.x);
        float2 p1 = __half22float2(*(__half2*)&zv.y);
        float2 p2 = __half22float2(*(__half2*)&zv.z);
        float2 p3 = __half22float2(*(__half2*)&zv.w);
        acc[0] += wt * p0.x; acc[1] += wt * p0.y;
        acc[2] += wt * p1.x; acc[3] += wt * p1.y;
        acc[4] += wt * p2.x; acc[5] += wt * p2.y;
        acc[6] += wt * p3.x; acc[7] += wt * p3.y;
    }

    const float4* bb = (const float4*)(b1 + lane * 8);
    float4 bv0 = bb[0], bv1 = bb[1];
    float r[8] = {acc[0] + bv0.x, acc[1] + bv0.y, acc[2] + bv0.z, acc[3] + bv0.w,
                  acc[4] + bv1.x, acc[5] + bv1.y, acc[6] + bv1.z, acc[7] + bv1.w};
#pragma unroll
    for (int i = 0; i < 8; i++) r[i] = r[i] > 0.f ? r[i] : expm1f(r[i]);
    uint4 hv = make_uint4(pack_h2(r[0], r[1]), pack_h2(r[2], r[3]),
                          pack_h2(r[4], r[5]), pack_h2(r[6], r[7]));
    *(uint4*)(g_h1h + (size_t)dst * HC + lane * 8) = hv;
}

// ---------------- mma.sync GEMM2: z2 = h1h @ W2, fp16 A + split-fp16 B -------
// CTA: 256 thr (8 warps), tile 128(M) x 32(N); warp = 16 rows x 32 cols.
// A staged via cp.async from fp16 h1. smem: BH 0..16K | BL 16K..32K |
// A-buf0 32K..40K | A-buf1 40K..48K
__global__ __launch_bounds__(256, 2) void mmagemm2(const float* __restrict__ a_src2,
                                                   const float* __restrict__ a_dst2) {
    extern __shared__ char sm2[];
    uint32_t base = smem_u32(sm2);

    int tid = threadIdx.x, lane = tid & 31, wid = tid >> 5;
    int row0 = blockIdx.x * 128;

    int r0s = tid >> 2,         c0s = (tid & 3) << 3;
    int r1s = (tid + 256) >> 2, c1s = (tid & 3) << 3;
    uint32_t swA0 = swz(r0s, c0s), swA1 = swz(r1s, c1s);

    // ---- stage B once: [32][256] fp16 hi/lo in 8 chunks of [32][32] ----
#pragma unroll
    for (int i = 0; i < 4; i++) {
        int f = tid + i * 256;
        int n = f >> 5, c8 = (f & 31) << 3;
        uint4 vh = *(const uint4*)(g_w2h + (size_t)n * N_FEAT + c8);
        uint4 vl = *(const uint4*)(g_w2l + (size_t)n * N_FEAT + c8);
        uint32_t so = (uint32_t)(c8 >> 5) * 2048 + swz(n, c8 & 31);
        *(uint4*)(sm2 + so)          = vh;
        *(uint4*)(sm2 + 16384 + so)  = vl;
    }

    float C[4][4];
#pragma unroll
    for (int nt = 0; nt < 4; nt++)
#pragma unroll
        for (int j = 0; j < 4; j++) C[nt][j] = 0.f;

    auto issueA = [&](int kt, uint32_t bufoff) {
#pragma unroll
        for (int i = 0; i < 2; i++) {
            int r = i ? r1s : r0s, c = i ? c1s : c0s;
            cp16(base + bufoff + (i ? swA1 : swA0),
                 g_h1h + (size_t)(row0 + r) * N_FEAT + kt * 32 + c);
        }
    };

    issueA(0, 32768);
    cp_commit();
    cp_wait0();
    __syncthreads();

    for (int kt = 0; kt < 8; kt++) {
        uint32_t cur = 32768 + (uint32_t)(kt & 1) * 8192;
        uint32_t nxt = 32768 + 8192 - (cur - 32768);
        if (kt < 7) {
            issueA(kt + 1, nxt);
            cp_commit();
        }

        uint32_t uA = base + cur;
        uint32_t bchunk = (uint32_t)kt * 2048;
#pragma unroll
        for (int ki = 0; ki < 2; ki++) {
            uint32_t Ah[4], Bh[4][2], Bl[4][2];
            int g = lane >> 3, lr = lane & 7;
            int arow = wid * 16 + (g & 1) * 8 + lr;
            int ak = ki * 16 + (g >> 1) * 8;
            ldsm_x4(Ah[0], Ah[1], Ah[2], Ah[3], uA + swz(arow, ak));

            int bn = lane & 7;
            int bk = ki * 16 + ((lane >> 3) & 1) * 8;
#pragma unroll
            for (int nt = 0; nt < 4; nt++) {
                uint32_t so = bchunk + swz(nt * 8 + bn, bk);
                ldsm_x2(Bh[nt][0], Bh[nt][1], base + so);
                ldsm_x2(Bl[nt][0], Bl[nt][1], base + 16384 + so);
            }
#pragma unroll
            for (int nt = 0; nt < 4; nt++) {
                mma16816h(C[nt], Ah, Bh[nt]);
                mma16816h(C[nt], Ah, Bl[nt]);
            }
        }
        if (kt < 7) cp_wait0();
        __syncthreads();
    }

    // ---- epilogue: z2(fp16) stores + fused alpha2 (rows cover all 32 cols) --
    int q = lane & 3, hrow = lane >> 2;
    float asr[8], adr[8];
#pragma unroll
    for (int nt = 0; nt < 4; nt++)
#pragma unroll
        for (int j = 0; j < 2; j++) {
            int col = nt * 8 + q * 2 + j;
            asr[nt * 2 + j] = __ldg(a_src2 + col);
            adr[nt * 2 + j] = __ldg(a_dst2 + col);
        }

    int ra = row0 + wid * 16 + hrow;
    int rb = ra + 8;
    float sa = 0.f, da = 0.f, sb2 = 0.f, db = 0.f;
#pragma unroll
    for (int nt = 0; nt < 4; nt++) {
        sa  += C[nt][0] * asr[nt * 2] + C[nt][1] * asr[nt * 2 + 1];
        da  += C[nt][0] * adr[nt * 2] + C[nt][1] * adr[nt * 2 + 1];
        sb2 += C[nt][2] * asr[nt * 2] + C[nt][3] * asr[nt * 2 + 1];
        db  += C[nt][2] * adr[nt * 2] + C[nt][3] * adr[nt * 2 + 1];
    }
#pragma unroll
    for (int o = 1; o <= 2; o <<= 1) {
        sa  += __shfl_xor_sync(0xFFFFFFFFu, sa, o);
        da  += __shfl_xor_sync(0xFFFFFFFFu, da, o);
        sb2 += __shfl_xor_sync(0xFFFFFFFFu, sb2, o);
        db  += __shfl_xor_sync(0xFFFFFFFFu, db, o);
    }
    if (q == 0 && ra < N_NODES) { g_as2[ra] = sa;  g_ad2[ra] = da; }
    if (q == 0 && rb < N_NODES) { g_as2[rb] = sb2; g_ad2[rb] = db; }

#pragma unroll
    for (int nt = 0; nt < 4; nt++) {
        int col = nt * 8 + q * 2;
        if (ra < N_NODES)
            *(__half2*)(g_z2h + (size_t)ra * NC + col) =
                __floats2half2_rn(C[nt][0], C[nt][1]);
        if (rb < N_NODES)
            *(__half2*)(g_z2h + (size_t)rb * NC + col) =
                __floats2half2_rn(C[nt][2], C[nt][3]);
    }
}

// ---------------- fused layer-2 GAT + bias -> out ----------------------------
__global__ __launch_bounds__(256) void gat2_fused(float* __restrict__ out,
                                                  const float* __restrict__ b2) {
    int lane = threadIdx.x & 31;
    int dst  = blockIdx.x * 8 + (threadIdx.x >> 5);
    if (dst >= N_NODES) return;
    int beg = g_rowptr[dst], end = g_rowptr[dst + 1];
    float adv = g_ad2[dst];

    float smv = 0.f;
    for (int j = beg + lane; j < end; j += 32)
        smv += __expf(lrelu(g_as2[g_csrc[j]] + adv));
#pragma unroll
    for (int o = 16; o; o >>= 1)
        smv += __shfl_xor_sync(0xFFFFFFFFu, smv, o);
    float inv = 1.f / smv;

    float acc = 0.f;
#pragma unroll 4
    for (int j = beg; j < end; j++) {
        int s = g_csrc[j];
        float wt = __expf(lrelu(g_as2[s] + adv)) * inv;
        acc += wt * __half2float(g_z2h[(size_t)s * NC + lane]);
    }
    out[(size_t)dst * NC + lane] = acc + b2[lane];
}

// ---------------- launch ------------------------------------------------------
extern "C" void kernel_launch(void* const* d_in, const int* in_sizes, int n_in,
                              void* d_out, int out_size) {
    const float* x      = (const float*)d_in[0];
    const void*  ei     = d_in[1];
    const float* W1     = (const float*)d_in[2];
    const float* a_src1 = (const float*)d_in[3];
    const float* a_dst1 = (const float*)d_in[4];
    const float* b1     = (const float*)d_in[5];
    const float* W2     = (const float*)d_in[6];
    const float* a_src2 = (const float*)d_in[7];
    const float* a_dst2 = (const float*)d_in[8];
    const float* b2     = (const float*)d_in[9];
    float* out = (float*)d_out;

    const int T = 256;
    const int SM_BYTES = 49152;

    cudaFuncSetAttribute(mmagemm1, cudaFuncAttributeMaxDynamicSharedMemorySize,
                         SM_BYTES);
    cudaFuncSetAttribute(mmagemm2, cudaFuncAttributeMaxDynamicSharedMemorySize,
                         SM_BYTES);

    // launches ordered so mmagemm1 is #4 (ncu capture slot)
    prep_kernel<<<(N_FEAT * HC + T - 1) / T, T>>>(W1, W2, ei);
    xprep_kernel<<<(N_NODES * N_FEAT / 8 + T - 1) / T, T>>>(x);
    decode_kernel<<<(TOT_E + T - 1) / T, T>>>(ei);
    {
        dim3 grid(2, (N_NODES + 127) / 128);
        mmagemm1<<<grid, 256, SM_BYTES>>>(a_src1, a_dst1);      // launch #4
    }
    scan1_kernel<<<NBLK, SCAN_B>>>();
    scan2_kernel<<<1, 1>>>();
    scan3_kernel<<<NBLK, SCAN_B>>>();
    scatter_kernel<<<(TOT_E + T - 1) / T, T>>>();

    gat1_fused<<<(N_NODES + 7) / 8, 256>>>(b1);
    mmagemm2<<<(N_NODES + 127) / 128, 256, SM_BYTES>>>(a_src2, a_dst2);
    gat2_fused<<<(N_NODES + 7) / 8, 256>>>(out, b2);
}

// round 16
// speedup vs baseline: 1.1285x; 1.1285x over previous
#include <cuda_runtime.h>
#include <cuda_bf16.h>
#include <cuda_fp16.h>
#include <stdint.h>
#include <math.h>

#define N_NODES 50000
#define N_PAD   50048
#define N_FEAT  256
#define HC      256     // N_HEADS * N_HID
#define NH      8
#define NC      32      // classes
#define N_EDGES 800000
#define TOT_E   (N_EDGES + N_NODES)   // 850000
#define SCAN_B  1024
#define NBLK    ((N_NODES + SCAN_B - 1) / SCAN_B)   // 49

// ---------------- scratch (__device__ globals; no runtime allocation) -------
__device__ __align__(16) __half g_z1h[(size_t)N_NODES * HC];   // 25.6 MB
__device__ __align__(16) __half g_h1h[(size_t)N_PAD * HC];     // 25.6 MB h1 fp16
__device__ __align__(16) float g_as1[N_NODES * NH];
__device__ __align__(16) float g_ad1[N_NODES * NH];
__device__ __align__(16) __half g_z2h[(size_t)N_NODES * NC];   // 3.2 MB
__device__            float g_as2[N_NODES];
__device__            float g_ad2[N_NODES];
__device__            int   g_src[TOT_E];
__device__            int   g_dst[TOT_E];
__device__            int   g_deg[N_NODES];
__device__            int   g_rowptr[N_NODES + 1];
__device__            int   g_wp[N_NODES];
__device__            int   g_csrc[TOT_E];
__device__            int   g_bsum[NBLK];
__device__            int   g_is64;
__device__ __align__(16) __half g_w1h[N_FEAT * HC];  // [N=256][K=256] fp16 hi
__device__ __align__(16) __half g_w1l[N_FEAT * HC];  // fp16 lo (residual)
__device__ __align__(16) __half g_w2h[NC * N_FEAT];  // [N=32][K=256]
__device__ __align__(16) __half g_w2l[NC * N_FEAT];

// ---------------- helpers ---------------------------------------------------
__device__ __forceinline__ float lrelu(float x) { return x > 0.f ? x : 0.2f * x; }

__device__ __forceinline__ unsigned int pack_h2(float a, float b) {
    __half2 p = __floats2half2_rn(a, b);
    return *reinterpret_cast<unsigned int*>(&p);
}
__device__ __forceinline__ uint32_t smem_u32(const void* p) {
    uint32_t a;
    asm("{ .reg .u64 t; cvta.to.shared.u64 t, %1; cvt.u32.u64 %0, t; }"
        : "=r"(a) : "l"(p));
    return a;
}
__device__ __forceinline__ void cp16(uint32_t s, const void* g) {
    asm volatile("cp.async.cg.shared.global [%0], [%1], 16;" :: "r"(s), "l"(g));
}
__device__ __forceinline__ void cp_commit() {
    asm volatile("cp.async.commit_group;");
}
__device__ __forceinline__ void cp_wait0() {
    asm volatile("cp.async.wait_group 0;" ::: "memory");
}
__device__ __forceinline__ void ldsm_x4(uint32_t& r0, uint32_t& r1,
                                        uint32_t& r2, uint32_t& r3, uint32_t addr) {
    asm volatile("ldmatrix.sync.aligned.m8n8.x4.shared.b16 {%0,%1,%2,%3}, [%4];"
                 : "=r"(r0), "=r"(r1), "=r"(r2), "=r"(r3) : "r"(addr));
}
__device__ __forceinline__ void ldsm_x2(uint32_t& r0, uint32_t& r1, uint32_t addr) {
    asm volatile("ldmatrix.sync.aligned.m8n8.x2.shared.b16 {%0,%1}, [%2];"
                 : "=r"(r0), "=r"(r1) : "r"(addr));
}
// f16 MMA: D(f32) += A(f16) x B(f16)
__device__ __forceinline__ void mma16816h(float* c, const uint32_t* a, const uint32_t* b) {
    asm volatile(
        "mma.sync.aligned.m16n8k16.row.col.f32.f16.f16.f32 "
        "{%0,%1,%2,%3}, {%4,%5,%6,%7}, {%8,%9}, {%0,%1,%2,%3};"
        : "+f"(c[0]), "+f"(c[1]), "+f"(c[2]), "+f"(c[3])
        : "r"(a[0]), "r"(a[1]), "r"(a[2]), "r"(a[3]), "r"(b[0]), "r"(b[1]));
}
// swizzled byte offset in a [rows][32] 16-bit tile (64B rows, chunk-XOR)
__device__ __forceinline__ uint32_t swz(int r, int k) {
    return (uint32_t)(r * 64 + ((((k >> 3) ^ ((r >> 1) & 3)) << 4) | ((k & 7) << 1)));
}

// ---------------- prep: edge-dtype detect + deg zero + W fp16 hi/lo splits ---
__global__ void prep_kernel(const float* __restrict__ W1,
                            const float* __restrict__ W2,
                            const void* __restrict__ ei) {
    int idx = blockIdx.x * blockDim.x + threadIdx.x;
    if (idx == 0) {
        const long long* e64 = (const long long*)ei;
        int ok = 1;
        for (int i = 0; i < 64; i++) {
            long long v = e64[i];
            if (v < 0 || v >= N_NODES) { ok = 0; break; }
        }
        g_is64 = ok;
    }
    if (idx < N_FEAT * HC) {
        int n = idx >> 8, k = idx & 255;
        float w = W1[k * HC + n];
        __half h = __float2half_rn(w);
        g_w1h[n * N_FEAT + k] = h;
        g_w1l[n * N_FEAT + k] = __float2half_rn(w - __half2float(h));
    }
    if (idx < NC * N_FEAT) {
        int n = idx >> 8, k = idx & 255;
        float w = W2[k * NC + n];
        __half h = __float2half_rn(w);
        g_w2h[n * N_FEAT + k] = h;
        g_w2l[n * N_FEAT + k] = __float2half_rn(w - __half2float(h));
    }
    if (idx < N_NODES) g_deg[idx] = 0;
}

__global__ void decode_kernel(const void* __restrict__ ei) {
    int e = blockIdx.x * blockDim.x + threadIdx.x;
    if (e >= TOT_E) return;
    int src, dst;
    if (e >= N_EDGES) {
        src = dst = e - N_EDGES;           // self loop
    } else if (g_is64) {
        const long long* p = (const long long*)ei;
        src = (int)p[e]; dst = (int)p[N_EDGES + e];
    } else {
        const int* p = (const int*)ei;
        src = p[e]; dst = p[N_EDGES + e];
    }
    g_src[e] = src;
    g_dst[e] = dst;
    atomicAdd(&g_deg[dst], 1);
}

// ---------------- multi-block exclusive scan of g_deg ------------------------
__global__ __launch_bounds__(SCAN_B) void scan1_kernel() {
    __shared__ int warp_sums[32];
    int tid = threadIdx.x, lane = tid & 31, wid = tid >> 5;
    int i = blockIdx.x * SCAN_B + tid;
    int v = (i < N_NODES) ? g_deg[i] : 0;
    int x = v;
#pragma unroll
    for (int o = 1; o < 32; o <<= 1) {
        int y = __shfl_up_sync(0xFFFFFFFFu, x, o);
        if (lane >= o) x += y;
    }
    if (lane == 31) warp_sums[wid] = x;
    __syncthreads();
    if (wid == 0) {
        int s = warp_sums[lane];
#pragma unroll
        for (int o = 1; o < 32; o <<= 1) {
            int y = __shfl_up_sync(0xFFFFFFFFu, s, o);
            if (lane >= o) s += y;
        }
        warp_sums[lane] = s;
    }
    __syncthreads();
    int excl = x - v + (wid > 0 ? warp_sums[wid - 1] : 0);
    if (i < N_NODES) g_rowptr[i] = excl;
    if (tid == SCAN_B - 1) g_bsum[blockIdx.x] = excl + v;
}

__global__ void scan2_kernel() {
    int run = 0;
    for (int b = 0; b < NBLK; b++) {
        int t = g_bsum[b];
        g_bsum[b] = run;
        run += t;
    }
}

__global__ __launch_bounds__(SCAN_B) void scan3_kernel() {
    int i = blockIdx.x * SCAN_B + threadIdx.x;
    if (i < N_NODES) {
        int r = g_rowptr[i] + g_bsum[blockIdx.x];
        g_rowptr[i] = r;
        g_wp[i] = r;
    }
    if (i == 0) g_rowptr[N_NODES] = TOT_E;
}

__global__ void scatter_kernel() {
    int e = blockIdx.x * blockDim.x + threadIdx.x;
    if (e >= TOT_E) return;
    int pos = atomicAdd(&g_wp[g_dst[e]], 1);
    g_csrc[pos] = g_src[e];
}

// ---------------- mma.sync GEMM1: z1 = x @ W1, fp16 A + split-fp16 B ---------
// CTA: 256 thr (8 warps), tile 128(M) x 128(N); warp tile 64x32 (one head).
// A converted in-kernel (reg prefetch, free under MMA latency); B via cp.async.
// Buffer layout (24K each): A 8K | BH 8K | BL 8K. Total smem 48K.
#define MG1_BUF 24576
__global__ __launch_bounds__(256, 2) void mmagemm1(const float* __restrict__ x,
                                                   const float* __restrict__ a_src,
                                                   const float* __restrict__ a_dst) {
    extern __shared__ char sm1[];
    uint32_t base = smem_u32(sm1);

    int tid  = threadIdx.x, lane = tid & 31, wid = tid >> 5;
    int bcol = blockIdx.x;                  // 0,1 -> n half
    int row0 = blockIdx.y * 128;
    int mwarp = wid >> 2, nwarp = wid & 3;  // 2 x 4 warp grid
    int n0 = bcol * 128;

    int r0s = tid >> 2,          c0s = (tid & 3) << 3;
    int r1s = (tid + 256) >> 2,  c1s = (tid & 3) << 3;
    uint32_t swA0 = swz(r0s, c0s), swA1 = swz(r1s, c1s);

    float C[4][4][4];
#pragma unroll
    for (int mt = 0; mt < 4; mt++)
#pragma unroll
        for (int nt = 0; nt < 4; nt++)
#pragma unroll
            for (int j = 0; j < 4; j++) C[mt][nt][j] = 0.f;

    float ar[2][8];

    auto loadA = [&](int kt) {
#pragma unroll
        for (int i = 0; i < 2; i++) {
            int r = i ? r1s : r0s, c = i ? c1s : c0s;
            int gr = row0 + r;
            float4 v0 = make_float4(0.f, 0.f, 0.f, 0.f), v1 = v0;
            if (gr < N_NODES) {
                const float* xp = x + (size_t)gr * N_FEAT + kt * 32 + c;
                v0 = *(const float4*)xp;
                v1 = *(const float4*)(xp + 4);
            }
            ar[i][0]=v0.x; ar[i][1]=v0.y; ar[i][2]=v0.z; ar[i][3]=v0.w;
            ar[i][4]=v1.x; ar[i][5]=v1.y; ar[i][6]=v1.z; ar[i][7]=v1.w;
        }
    };
    auto storeA = [&](uint32_t bufoff) {
#pragma unroll
        for (int i = 0; i < 2; i++) {
            uint4 hv = make_uint4(pack_h2(ar[i][0], ar[i][1]),
                                  pack_h2(ar[i][2], ar[i][3]),
                                  pack_h2(ar[i][4], ar[i][5]),
                                  pack_h2(ar[i][6], ar[i][7]));
            *(uint4*)(sm1 + bufoff + (i ? swA1 : swA0)) = hv;
        }
    };
    auto issueB = [&](int kt, uint32_t bufoff) {
#pragma unroll
        for (int i = 0; i < 2; i++) {
            int n = i ? r1s : r0s, c = i ? c1s : c0s;
            uint32_t so = i ? swA1 : swA0;
            cp16(base + bufoff + 8192 + so,
                 g_w1h + (size_t)(n0 + n) * N_FEAT + kt * 32 + c);
            cp16(base + bufoff + 16384 + so,
                 g_w1l + (size_t)(n0 + n) * N_FEAT + kt * 32 + c);
        }
    };

    // prologue: fill buffer 0
    loadA(0);
    issueB(0, 0);
    cp_commit();
    storeA(0);
    cp_wait0();
    __syncthreads();

    for (int kt = 0; kt < 8; kt++) {
        uint32_t cur = (uint32_t)(kt & 1) * MG1_BUF;
        uint32_t nxt = MG1_BUF - cur;
        if (kt < 7) {
            loadA(kt + 1);
            issueB(kt + 1, nxt);
            cp_commit();
        }
        uint32_t uA = base + cur;
        uint32_t uBh = uA + 8192, uBl = uA + 16384;

#pragma unroll
        for (int ki = 0; ki < 2; ki++) {
            uint32_t Ah[4][4], Bh[4][2], Bl[4][2];
            int g = lane >> 3, lr = lane & 7;
            int arow = mwarp * 64 + (g & 1) * 8 + lr;
            int ak = ki * 16 + (g >> 1) * 8;
#pragma unroll
            for (int mt = 0; mt < 4; mt++) {
                uint32_t so = swz(arow + mt * 16, ak);
                ldsm_x4(Ah[mt][0], Ah[mt][1], Ah[mt][2], Ah[mt][3], uA + so);
            }
            int bn = nwarp * 32 + (lane & 7);
            int bk = ki * 16 + ((lane >> 3) & 1) * 8;
#pragma unroll
            for (int nt = 0; nt < 4; nt++) {
                uint32_t so = swz(bn + nt * 8, bk);
                ldsm_x2(Bh[nt][0], Bh[nt][1], uBh + so);
                ldsm_x2(Bl[nt][0], Bl[nt][1], uBl + so);
            }
#pragma unroll
            for (int mt = 0; mt < 4; mt++)
#pragma unroll
                for (int nt = 0; nt < 4; nt++) {
                    mma16816h(C[mt][nt], Ah[mt], Bh[nt]);
                    mma16816h(C[mt][nt], Ah[mt], Bl[nt]);
                }
        }
        if (kt < 7) {
            storeA(nxt);
            cp_wait0();
        }
        __syncthreads();
    }

    // ---- epilogue: z1(fp16) stores + fused alpha1 dots (warp cols = 1 head) -
    int q = lane & 3, hrow = lane >> 2;
    int head = bcol * 4 + nwarp;
    float asr[8], adr[8];
#pragma unroll
    for (int nt = 0; nt < 4; nt++)
#pragma unroll
        for (int j = 0; j < 2; j++) {
            int col = head * 32 + nt * 8 + q * 2 + j;
            asr[nt * 2 + j] = __ldg(a_src + col);
            adr[nt * 2 + j] = __ldg(a_dst + col);
        }

#pragma unroll
    for (int mt = 0; mt < 4; mt++) {
        int ra = row0 + mwarp * 64 + mt * 16 + hrow;
        int rb = ra + 8;
        float sa = 0.f, da = 0.f, sb2 = 0.f, db = 0.f;
#pragma unroll
        for (int nt = 0; nt < 4; nt++) {
            sa  += C[mt][nt][0] * asr[nt * 2] + C[mt][nt][1] * asr[nt * 2 + 1];
            da  += C[mt][nt][0] * adr[nt * 2] + C[mt][nt][1] * adr[nt * 2 + 1];
            sb2 += C[mt][nt][2] * asr[nt * 2] + C[mt][nt][3] * asr[nt * 2 + 1];
            db  += C[mt][nt][2] * adr[nt * 2] + C[mt][nt][3] * adr[nt * 2 + 1];
        }
#pragma unroll
        for (int o = 1; o <= 2; o <<= 1) {
            sa  += __shfl_xor_sync(0xFFFFFFFFu, sa, o);
            da  += __shfl_xor_sync(0xFFFFFFFFu, da, o);
            sb2 += __shfl_xor_sync(0xFFFFFFFFu, sb2, o);
            db  += __shfl_xor_sync(0xFFFFFFFFu, db, o);
        }
        if (q == 0 && ra < N_NODES) { g_as1[ra * NH + head] = sa;  g_ad1[ra * NH + head] = da; }
        if (q == 0 && rb < N_NODES) { g_as1[rb * NH + head] = sb2; g_ad1[rb * NH + head] = db; }

#pragma unroll
        for (int nt = 0; nt < 4; nt++) {
            int col = head * 32 + nt * 8 + q * 2;
            if (ra < N_NODES)
                *(__half2*)(g_z1h + (size_t)ra * HC + col) =
                    __floats2half2_rn(C[mt][nt][0], C[mt][nt][1]);
            if (rb < N_NODES)
                *(__half2*)(g_z1h + (size_t)rb * HC + col) =
                    __floats2half2_rn(C[mt][nt][2], C[mt][nt][3]);
        }
    }
}

// ---------------- fused layer-1 GAT: softmax + aggregate + bias + ELU --------
// h1 stored directly as fp16 (same rounding point as old fp32-store+convert).
__global__ __launch_bounds__(256) void gat1_fused(const float* __restrict__ b1) {
    int lane = threadIdx.x & 31;
    int dst  = blockIdx.x * 8 + (threadIdx.x >> 5);
    if (dst >= N_NODES) return;
    int beg = g_rowptr[dst], end = g_rowptr[dst + 1];

    float ad[NH];
    {
        float4 d0 = *(const float4*)(g_ad1 + dst * NH);
        float4 d1 = *(const float4*)(g_ad1 + dst * NH + 4);
        ad[0]=d0.x; ad[1]=d0.y; ad[2]=d0.z; ad[3]=d0.w;
        ad[4]=d1.x; ad[5]=d1.y; ad[6]=d1.z; ad[7]=d1.w;
    }

    float sm[NH];
#pragma unroll
    for (int h = 0; h < NH; h++) sm[h] = 0.f;
    for (int j = beg + lane; j < end; j += 32) {
        int s = g_csrc[j];
        float4 s0 = *(const float4*)(g_as1 + s * NH);
        float4 s1 = *(const float4*)(g_as1 + s * NH + 4);
        float as[NH] = {s0.x, s0.y, s0.z, s0.w, s1.x, s1.y, s1.z, s1.w};
#pragma unroll
        for (int h = 0; h < NH; h++)
            sm[h] += __expf(lrelu(as[h] + ad[h]));
    }
#pragma unroll
    for (int h = 0; h < NH; h++)
#pragma unroll
        for (int o = 16; o; o >>= 1)
            sm[h] += __shfl_xor_sync(0xFFFFFFFFu, sm[h], o);

    int   hme  = lane >> 2;
    float invm = 1.f / sm[hme];
    float adm  = ad[hme];

    float acc[8];
#pragma unroll
    for (int i = 0; i < 8; i++) acc[i] = 0.f;
#pragma unroll 8
    for (int j = beg; j < end; j++) {
        int s = g_csrc[j];
        float wt = __expf(lrelu(g_as1[s * NH + hme] + adm)) * invm;
        uint4 zv = *((const uint4*)(g_z1h + (size_t)s * HC) + lane);
        float2 p0 = __half22float2(*(__half2*)&zv.x);
        float2 p1 = __half22float2(*(__half2*)&zv.y);
        float2 p2 = __half22float2(*(__half2*)&zv.z);
        float2 p3 = __half22float2(*(__half2*)&zv.w);
        acc[0] += wt * p0.x; acc[1] += wt * p0.y;
        acc[2] += wt * p1.x; acc[3] += wt * p1.y;
        acc[4] += wt * p2.x; acc[5] += wt * p2.y;
        acc[6] += wt * p3.x; acc[7] += wt * p3.y;
    }

    const float4* bb = (const float4*)(b1 + lane * 8);
    float4 bv0 = bb[0], bv1 = bb[1];
    float r[8] = {acc[0] + bv0.x, acc[1] + bv0.y, acc[2] + bv0.z, acc[3] + bv0.w,
                  acc[4] + bv1.x, acc[5] + bv1.y, acc[6] + bv1.z, acc[7] + bv1.w};
#pragma unroll
    for (int i = 0; i < 8; i++) r[i] = r[i] > 0.f ? r[i] : expm1f(r[i]);
    uint4 hv = make_uint4(pack_h2(r[0], r[1]), pack_h2(r[2], r[3]),
                          pack_h2(r[4], r[5]), pack_h2(r[6], r[7]));
    *(uint4*)(g_h1h + (size_t)dst * HC + lane * 8) = hv;
}

// ---------------- mma.sync GEMM2: z2 = h1h @ W2, fp16 A + split-fp16 B -------
// CTA: 256 thr (8 warps), tile 128(M) x 32(N); A via cp.async from fp16 h1.
// smem: BH 0..16K | BL 16K..32K | A-buf0 32K..40K | A-buf1 40K..48K
__global__ __launch_bounds__(256, 2) void mmagemm2(const float* __restrict__ a_src2,
                                                   const float* __restrict__ a_dst2) {
    extern __shared__ char sm2[];
    uint32_t base = smem_u32(sm2);

    int tid = threadIdx.x, lane = tid & 31, wid = tid >> 5;
    int row0 = blockIdx.x * 128;

    int r0s = tid >> 2,         c0s = (tid & 3) << 3;
    int r1s = (tid + 256) >> 2, c1s = (tid & 3) << 3;
    uint32_t swA0 = swz(r0s, c0s), swA1 = swz(r1s, c1s);

    // ---- stage B once: [32][256] fp16 hi/lo in 8 chunks of [32][32] ----
#pragma unroll
    for (int i = 0; i < 4; i++) {
        int f = tid + i * 256;
        int n = f >> 5, c8 = (f & 31) << 3;
        uint4 vh = *(const uint4*)(g_w2h + (size_t)n * N_FEAT + c8);
        uint4 vl = *(const uint4*)(g_w2l + (size_t)n * N_FEAT + c8);
        uint32_t so = (uint32_t)(c8 >> 5) * 2048 + swz(n, c8 & 31);
        *(uint4*)(sm2 + so)          = vh;
        *(uint4*)(sm2 + 16384 + so)  = vl;
    }

    float C[4][4];
#pragma unroll
    for (int nt = 0; nt < 4; nt++)
#pragma unroll
        for (int j = 0; j < 4; j++) C[nt][j] = 0.f;

    auto issueA = [&](int kt, uint32_t bufoff) {
#pragma unroll
        for (int i = 0; i < 2; i++) {
            int r = i ? r1s : r0s, c = i ? c1s : c0s;
            cp16(base + bufoff + (i ? swA1 : swA0),
                 g_h1h + (size_t)(row0 + r) * N_FEAT + kt * 32 + c);
        }
    };

    issueA(0, 32768);
    cp_commit();
    cp_wait0();
    __syncthreads();

    for (int kt = 0; kt < 8; kt++) {
        uint32_t cur = 32768 + (uint32_t)(kt & 1) * 8192;
        uint32_t nxt = 32768 + 8192 - (cur - 32768);
        if (kt < 7) {
            issueA(kt + 1, nxt);
            cp_commit();
        }

        uint32_t uA = base + cur;
        uint32_t bchunk = (uint32_t)kt * 2048;
#pragma unroll
        for (int ki = 0; ki < 2; ki++) {
            uint32_t Ah[4], Bh[4][2], Bl[4][2];
            int g = lane >> 3, lr = lane & 7;
            int arow = wid * 16 + (g & 1) * 8 + lr;
            int ak = ki * 16 + (g >> 1) * 8;
            ldsm_x4(Ah[0], Ah[1], Ah[2], Ah[3], uA + swz(arow, ak));

            int bn = lane & 7;
            int bk = ki * 16 + ((lane >> 3) & 1) * 8;
#pragma unroll
            for (int nt = 0; nt < 4; nt++) {
                uint32_t so = bchunk + swz(nt * 8 + bn, bk);
                ldsm_x2(Bh[nt][0], Bh[nt][1], base + so);
                ldsm_x2(Bl[nt][0], Bl[nt][1], base + 16384 + so);
            }
#pragma unroll
            for (int nt = 0; nt < 4; nt++) {
                mma16816h(C[nt], Ah, Bh[nt]);
                mma16816h(C[nt], Ah, Bl[nt]);
            }
        }
        if (kt < 7) cp_wait0();
        __syncthreads();
    }

    // ---- epilogue: z2(fp16) stores + fused alpha2 (rows cover all 32 cols) --
    int q = lane & 3, hrow = lane >> 2;
    float asr[8], adr[8];
#pragma unroll
    for (int nt = 0; nt < 4; nt++)
#pragma unroll
        for (int j = 0; j < 2; j++) {
            int col = nt * 8 + q * 2 + j;
            asr[nt * 2 + j] = __ldg(a_src2 + col);
            adr[nt * 2 + j] = __ldg(a_dst2 + col);
        }

    int ra = row0 + wid * 16 + hrow;
    int rb = ra + 8;
    float sa = 0.f, da = 0.f, sb2 = 0.f, db = 0.f;
#pragma unroll
    for (int nt = 0; nt < 4; nt++) {
        sa  += C[nt][0] * asr[nt * 2] + C[nt][1] * asr[nt * 2 + 1];
        da  += C[nt][0] * adr[nt * 2] + C[nt][1] * adr[nt * 2 + 1];
        sb2 += C[nt][2] * asr[nt * 2] + C[nt][3] * asr[nt * 2 + 1];
        db  += C[nt][2] * adr[nt * 2] + C[nt][3] * adr[nt * 2 + 1];
    }
#pragma unroll
    for (int o = 1; o <= 2; o <<= 1) {
        sa  += __shfl_xor_sync(0xFFFFFFFFu, sa, o);
        da  += __shfl_xor_sync(0xFFFFFFFFu, da, o);
        sb2 += __shfl_xor_sync(0xFFFFFFFFu, sb2, o);
        db  += __shfl_xor_sync(0xFFFFFFFFu, db, o);
    }
    if (q == 0 && ra < N_NODES) { g_as2[ra] = sa;  g_ad2[ra] = da; }
    if (q == 0 && rb < N_NODES) { g_as2[rb] = sb2; g_ad2[rb] = db; }

#pragma unroll
    for (int nt = 0; nt < 4; nt++) {
        int col = nt * 8 + q * 2;
        if (ra < N_NODES)
            *(__half2*)(g_z2h + (size_t)ra * NC + col) =
                __floats2half2_rn(C[nt][0], C[nt][1]);
        if (rb < N_NODES)
            *(__half2*)(g_z2h + (size_t)rb * NC + col) =
                __floats2half2_rn(C[nt][2], C[nt][3]);
    }
}

// ---------------- fused layer-2 GAT + bias -> out ----------------------------
__global__ __launch_bounds__(256) void gat2_fused(float* __restrict__ out,
                                                  const float* __restrict__ b2) {
    int lane = threadIdx.x & 31;
    int dst  = blockIdx.x * 8 + (threadIdx.x >> 5);
    if (dst >= N_NODES) return;
    int beg = g_rowptr[dst], end = g_rowptr[dst + 1];
    float adv = g_ad2[dst];

    float smv = 0.f;
    for (int j = beg + lane; j < end; j += 32)
        smv += __expf(lrelu(g_as2[g_csrc[j]] + adv));
#pragma unroll
    for (int o = 16; o; o >>= 1)
        smv += __shfl_xor_sync(0xFFFFFFFFu, smv, o);
    float inv = 1.f / smv;

    float acc = 0.f;
#pragma unroll 4
    for (int j = beg; j < end; j++) {
        int s = g_csrc[j];
        float wt = __expf(lrelu(g_as2[s] + adv)) * inv;
        acc += wt * __half2float(g_z2h[(size_t)s * NC + lane]);
    }
    out[(size_t)dst * NC + lane] = acc + b2[lane];
}

// ---------------- launch ------------------------------------------------------
extern "C" void kernel_launch(void* const* d_in, const int* in_sizes, int n_in,
                              void* d_out, int out_size) {
    const float* x      = (const float*)d_in[0];
    const void*  ei     = d_in[1];
    const float* W1     = (const float*)d_in[2];
    const float* a_src1 = (const float*)d_in[3];
    const float* a_dst1 = (const float*)d_in[4];
    const float* b1     = (const float*)d_in[5];
    const float* W2     = (const float*)d_in[6];
    const float* a_src2 = (const float*)d_in[7];
    const float* a_dst2 = (const float*)d_in[8];
    const float* b2     = (const float*)d_in[9];
    float* out = (float*)d_out;

    const int T = 256;
    const int SM_BYTES = 49152;

    // one-time host-side resources (no device memory; identical captured
    // work on every call)
    static cudaStream_t s_side = nullptr;
    static cudaEvent_t  s_fork = nullptr, s_join = nullptr;
    if (s_side == nullptr) {
        cudaStreamCreateWithFlags(&s_side, cudaStreamNonBlocking);
        cudaEventCreateWithFlags(&s_fork, cudaEventDisableTiming);
        cudaEventCreateWithFlags(&s_join, cudaEventDisableTiming);
        cudaFuncSetAttribute(mmagemm1,
                             cudaFuncAttributeMaxDynamicSharedMemorySize, SM_BYTES);
        cudaFuncSetAttribute(mmagemm2,
                             cudaFuncAttributeMaxDynamicSharedMemorySize, SM_BYTES);
    }

    // main stream: prep -> (fork) -> mmagemm1 ... ; side stream: CSR build
    prep_kernel<<<(N_FEAT * HC + T - 1) / T, T>>>(W1, W2, ei);
    cudaEventRecord(s_fork, 0);
    cudaStreamWaitEvent(s_side, s_fork, 0);

    decode_kernel<<<(TOT_E + T - 1) / T, T, 0, s_side>>>(ei);
    scan1_kernel<<<NBLK, SCAN_B, 0, s_side>>>();
    {
        dim3 grid(2, (N_NODES + 127) / 128);
        mmagemm1<<<grid, 256, SM_BYTES>>>(x, a_src1, a_dst1);   // launch #4
    }
    scan2_kernel<<<1, 1, 0, s_side>>>();
    scan3_kernel<<<NBLK, SCAN_B, 0, s_side>>>();
    scatter_kernel<<<(TOT_E + T - 1) / T, T, 0, s_side>>>();
    cudaEventRecord(s_join, s_side);
    cudaStreamWaitEvent(0, s_join, 0);

    gat1_fused<<<(N_NODES + 7) / 8, 256>>>(b1);
    mmagemm2<<<(N_NODES + 127) / 128, 256, SM_BYTES>>>(a_src2, a_dst2);
    gat2_fused<<<(N_NODES + 7) / 8, 256>>>(out, b2);
}

// round 17
// speedup vs baseline: 1.2750x; 1.1298x over previous
#include <cuda_runtime.h>
#include <cuda_bf16.h>
#include <cuda_fp16.h>
#include <stdint.h>
#include <math.h>

#define N_NODES 50000
#define N_PAD   50048
#define N_FEAT  256
#define HC      256     // N_HEADS * N_HID
#define NH      8
#define NC      32      // classes
#define N_EDGES 800000
#define TOT_E   (N_EDGES + N_NODES)   // 850000
#define SCAN_B  1024
#define NBLK    ((N_NODES + SCAN_B - 1) / SCAN_B)   // 49

// ---------------- scratch (__device__ globals; no runtime allocation) -------
__device__ __align__(16) __half g_z1h[(size_t)N_NODES * HC];   // 25.6 MB
__device__ __align__(16) __half g_h1h[(size_t)N_PAD * HC];     // 25.6 MB h1 fp16
__device__ __align__(16) float g_as1[N_NODES * NH];
__device__ __align__(16) float g_ad1[N_NODES * NH];
__device__ __align__(16) __half g_z2h[(size_t)N_NODES * NC];   // 3.2 MB
__device__            float g_as2[N_NODES];
__device__            float g_ad2[N_NODES];
__device__            int   g_src[TOT_E];
__device__            int   g_dst[TOT_E];
__device__            int   g_deg[N_NODES];
__device__            int   g_rowptr[N_NODES + 1];
__device__            int   g_wp[N_NODES];
__device__            int   g_csrc[TOT_E];
__device__            int   g_bsum[NBLK];
__device__            int   g_is64;
__device__ __align__(16) __half g_w1h[N_FEAT * HC];  // [N=256][K=256] fp16 hi
__device__ __align__(16) __half g_w1l[N_FEAT * HC];  // fp16 lo (residual)
__device__ __align__(16) __half g_w2h[NC * N_FEAT];  // [N=32][K=256]
__device__ __align__(16) __half g_w2l[NC * N_FEAT];

// ---------------- helpers ---------------------------------------------------
__device__ __forceinline__ float lrelu(float x) { return x > 0.f ? x : 0.2f * x; }

__device__ __forceinline__ unsigned int pack_h2(float a, float b) {
    __half2 p = __floats2half2_rn(a, b);
    return *reinterpret_cast<unsigned int*>(&p);
}
__device__ __forceinline__ uint32_t smem_u32(const void* p) {
    uint32_t a;
    asm("{ .reg .u64 t; cvta.to.shared.u64 t, %1; cvt.u32.u64 %0, t; }"
        : "=r"(a) : "l"(p));
    return a;
}
__device__ __forceinline__ void cp16(uint32_t s, const void* g) {
    asm volatile("cp.async.cg.shared.global [%0], [%1], 16;" :: "r"(s), "l"(g));
}
__device__ __forceinline__ void cp_commit() {
    asm volatile("cp.async.commit_group;");
}
__device__ __forceinline__ void cp_wait0() {
    asm volatile("cp.async.wait_group 0;" ::: "memory");
}
__device__ __forceinline__ void ldsm_x4(uint32_t& r0, uint32_t& r1,
                                        uint32_t& r2, uint32_t& r3, uint32_t addr) {
    asm volatile("ldmatrix.sync.aligned.m8n8.x4.shared.b16 {%0,%1,%2,%3}, [%4];"
                 : "=r"(r0), "=r"(r1), "=r"(r2), "=r"(r3) : "r"(addr));
}
__device__ __forceinline__ void ldsm_x2(uint32_t& r0, uint32_t& r1, uint32_t addr) {
    asm volatile("ldmatrix.sync.aligned.m8n8.x2.shared.b16 {%0,%1}, [%2];"
                 : "=r"(r0), "=r"(r1) : "r"(addr));
}
// f16 MMA: D(f32) += A(f16) x B(f16)
__device__ __forceinline__ void mma16816h(float* c, const uint32_t* a, const uint32_t* b) {
    asm volatile(
        "mma.sync.aligned.m16n8k16.row.col.f32.f16.f16.f32 "
        "{%0,%1,%2,%3}, {%4,%5,%6,%7}, {%8,%9}, {%0,%1,%2,%3};"
        : "+f"(c[0]), "+f"(c[1]), "+f"(c[2]), "+f"(c[3])
        : "r"(a[0]), "r"(a[1]), "r"(a[2]), "r"(a[3]), "r"(b[0]), "r"(b[1]));
}
// swizzled byte offset in a [rows][32] 16-bit tile (64B rows, chunk-XOR)
__device__ __forceinline__ uint32_t swz(int r, int k) {
    return (uint32_t)(r * 64 + ((((k >> 3) ^ ((r >> 1) & 3)) << 4) | ((k & 7) << 1)));
}

// ---------------- prep: edge-dtype detect + deg zero + W fp16 hi/lo splits ---
__global__ void prep_kernel(const float* __restrict__ W1,
                            const float* __restrict__ W2,
                            const void* __restrict__ ei) {
    int idx = blockIdx.x * blockDim.x + threadIdx.x;
    if (idx == 0) {
        const long long* e64 = (const long long*)ei;
        int ok = 1;
        for (int i = 0; i < 64; i++) {
            long long v = e64[i];
            if (v < 0 || v >= N_NODES) { ok = 0; break; }
        }
        g_is64 = ok;
    }
    if (idx < N_FEAT * HC) {
        int n = idx >> 8, k = idx & 255;
        float w = W1[k * HC + n];
        __half h = __float2half_rn(w);
        g_w1h[n * N_FEAT + k] = h;
        g_w1l[n * N_FEAT + k] = __float2half_rn(w - __half2float(h));
    }
    if (idx < NC * N_FEAT) {
        int n = idx >> 8, k = idx & 255;
        float w = W2[k * NC + n];
        __half h = __float2half_rn(w);
        g_w2h[n * N_FEAT + k] = h;
        g_w2l[n * N_FEAT + k] = __float2half_rn(w - __half2float(h));
    }
    if (idx < N_NODES) g_deg[idx] = 0;
}

__global__ void decode_kernel(const void* __restrict__ ei) {
    int e = blockIdx.x * blockDim.x + threadIdx.x;
    if (e >= TOT_E) return;
    int src, dst;
    if (e >= N_EDGES) {
        src = dst = e - N_EDGES;           // self loop
    } else if (g_is64) {
        const long long* p = (const long long*)ei;
        src = (int)p[e]; dst = (int)p[N_EDGES + e];
    } else {
        const int* p = (const int*)ei;
        src = p[e]; dst = p[N_EDGES + e];
    }
    g_src[e] = src;
    g_dst[e] = dst;
    atomicAdd(&g_deg[dst], 1);
}

// ---------------- multi-block exclusive scan of g_deg ------------------------
__global__ __launch_bounds__(SCAN_B) void scan1_kernel() {
    __shared__ int warp_sums[32];
    int tid = threadIdx.x, lane = tid & 31, wid = tid >> 5;
    int i = blockIdx.x * SCAN_B + tid;
    int v = (i < N_NODES) ? g_deg[i] : 0;
    int x = v;
#pragma unroll
    for (int o = 1; o < 32; o <<= 1) {
        int y = __shfl_up_sync(0xFFFFFFFFu, x, o);
        if (lane >= o) x += y;
    }
    if (lane == 31) warp_sums[wid] = x;
    __syncthreads();
    if (wid == 0) {
        int s = warp_sums[lane];
#pragma unroll
        for (int o = 1; o < 32; o <<= 1) {
            int y = __shfl_up_sync(0xFFFFFFFFu, s, o);
            if (lane >= o) s += y;
        }
        warp_sums[lane] = s;
    }
    __syncthreads();
    int excl = x - v + (wid > 0 ? warp_sums[wid - 1] : 0);
    if (i < N_NODES) g_rowptr[i] = excl;
    if (tid == SCAN_B - 1) g_bsum[blockIdx.x] = excl + v;
}

__global__ void scan2_kernel() {
    int run = 0;
    for (int b = 0; b < NBLK; b++) {
        int t = g_bsum[b];
        g_bsum[b] = run;
        run += t;
    }
}

__global__ __launch_bounds__(SCAN_B) void scan3_kernel() {
    int i = blockIdx.x * SCAN_B + threadIdx.x;
    if (i < N_NODES) {
        int r = g_rowptr[i] + g_bsum[blockIdx.x];
        g_rowptr[i] = r;
        g_wp[i] = r;
    }
    if (i == 0) g_rowptr[N_NODES] = TOT_E;
}

__global__ void scatter_kernel() {
    int e = blockIdx.x * blockDim.x + threadIdx.x;
    if (e >= TOT_E) return;
    int pos = atomicAdd(&g_wp[g_dst[e]], 1);
    g_csrc[pos] = g_src[e];
}

// ---------------- mma.sync GEMM1: z1 = x @ W1, fp16 A + split-fp16 B ---------
// CTA: 256 thr (8 warps), tile 128(M) x 128(N); warp tile 64x32 (one head).
// A converted in-kernel; B via cp.async. Double-buffered (24K each).
#define MG1_BUF 24576
__global__ __launch_bounds__(256, 2) void mmagemm1(const float* __restrict__ x,
                                                   const float* __restrict__ a_src,
                                                   const float* __restrict__ a_dst) {
    extern __shared__ char sm1[];
    uint32_t base = smem_u32(sm1);

    int tid  = threadIdx.x, lane = tid & 31, wid = tid >> 5;
    int bcol = blockIdx.x;                  // 0,1 -> n half
    int row0 = blockIdx.y * 128;
    int mwarp = wid >> 2, nwarp = wid & 3;  // 2 x 4 warp grid
    int n0 = bcol * 128;

    int r0s = tid >> 2,          c0s = (tid & 3) << 3;
    int r1s = (tid + 256) >> 2,  c1s = (tid & 3) << 3;
    uint32_t swA0 = swz(r0s, c0s), swA1 = swz(r1s, c1s);

    float C[4][4][4];
#pragma unroll
    for (int mt = 0; mt < 4; mt++)
#pragma unroll
        for (int nt = 0; nt < 4; nt++)
#pragma unroll
            for (int j = 0; j < 4; j++) C[mt][nt][j] = 0.f;

    float ar[2][8];

    auto loadA = [&](int kt) {
#pragma unroll
        for (int i = 0; i < 2; i++) {
            int r = i ? r1s : r0s, c = i ? c1s : c0s;
            int gr = row0 + r;
            float4 v0 = make_float4(0.f, 0.f, 0.f, 0.f), v1 = v0;
            if (gr < N_NODES) {
                const float* xp = x + (size_t)gr * N_FEAT + kt * 32 + c;
                v0 = *(const float4*)xp;
                v1 = *(const float4*)(xp + 4);
            }
            ar[i][0]=v0.x; ar[i][1]=v0.y; ar[i][2]=v0.z; ar[i][3]=v0.w;
            ar[i][4]=v1.x; ar[i][5]=v1.y; ar[i][6]=v1.z; ar[i][7]=v1.w;
        }
    };
    auto storeA = [&](uint32_t bufoff) {
#pragma unroll
        for (int i = 0; i < 2; i++) {
            uint4 hv = make_uint4(pack_h2(ar[i][0], ar[i][1]),
                                  pack_h2(ar[i][2], ar[i][3]),
                                  pack_h2(ar[i][4], ar[i][5]),
                                  pack_h2(ar[i][6], ar[i][7]));
            *(uint4*)(sm1 + bufoff + (i ? swA1 : swA0)) = hv;
        }
    };
    auto issueB = [&](int kt, uint32_t bufoff) {
#pragma unroll
        for (int i = 0; i < 2; i++) {
            int n = i ? r1s : r0s, c = i ? c1s : c0s;
            uint32_t so = i ? swA1 : swA0;
            cp16(base + bufoff + 8192 + so,
                 g_w1h + (size_t)(n0 + n) * N_FEAT + kt * 32 + c);
            cp16(base + bufoff + 16384 + so,
                 g_w1l + (size_t)(n0 + n) * N_FEAT + kt * 32 + c);
        }
    };

    // prologue: fill buffer 0
    loadA(0);
    issueB(0, 0);
    cp_commit();
    storeA(0);
    cp_wait0();
    __syncthreads();

    for (int kt = 0; kt < 8; kt++) {
        uint32_t cur = (uint32_t)(kt & 1) * MG1_BUF;
        uint32_t nxt = MG1_BUF - cur;
        if (kt < 7) {
            loadA(kt + 1);
            issueB(kt + 1, nxt);
            cp_commit();
        }
        uint32_t uA = base + cur;
        uint32_t uBh = uA + 8192, uBl = uA + 16384;

#pragma unroll
        for (int ki = 0; ki < 2; ki++) {
            uint32_t Ah[4][4], Bh[4][2], Bl[4][2];
            int g = lane >> 3, lr = lane & 7;
            int arow = mwarp * 64 + (g & 1) * 8 + lr;
            int ak = ki * 16 + (g >> 1) * 8;
#pragma unroll
            for (int mt = 0; mt < 4; mt++) {
                uint32_t so = swz(arow + mt * 16, ak);
                ldsm_x4(Ah[mt][0], Ah[mt][1], Ah[mt][2], Ah[mt][3], uA + so);
            }
            int bn = nwarp * 32 + (lane & 7);
            int bk = ki * 16 + ((lane >> 3) & 1) * 8;
#pragma unroll
            for (int nt = 0; nt < 4; nt++) {
                uint32_t so = swz(bn + nt * 8, bk);
                ldsm_x2(Bh[nt][0], Bh[nt][1], uBh + so);
                ldsm_x2(Bl[nt][0], Bl[nt][1], uBl + so);
            }
#pragma unroll
            for (int mt = 0; mt < 4; mt++)
#pragma unroll
                for (int nt = 0; nt < 4; nt++) {
                    mma16816h(C[mt][nt], Ah[mt], Bh[nt]);
                    mma16816h(C[mt][nt], Ah[mt], Bl[nt]);
                }
        }
        if (kt < 7) {
            storeA(nxt);
            cp_wait0();
        }
        __syncthreads();
    }

    // ---- epilogue: z1(fp16) stores + fused alpha1 dots (warp cols = 1 head) -
    int q = lane & 3, hrow = lane >> 2;
    int head = bcol * 4 + nwarp;
    float asr[8], adr[8];
#pragma unroll
    for (int nt = 0; nt < 4; nt++)
#pragma unroll
        for (int j = 0; j < 2; j++) {
            int col = head * 32 + nt * 8 + q * 2 + j;
            asr[nt * 2 + j] = __ldg(a_src + col);
            adr[nt * 2 + j] = __ldg(a_dst + col);
        }

#pragma unroll
    for (int mt = 0; mt < 4; mt++) {
        int ra = row0 + mwarp * 64 + mt * 16 + hrow;
        int rb = ra + 8;
        float sa = 0.f, da = 0.f, sb2 = 0.f, db = 0.f;
#pragma unroll
        for (int nt = 0; nt < 4; nt++) {
            sa  += C[mt][nt][0] * asr[nt * 2] + C[mt][nt][1] * asr[nt * 2 + 1];
            da  += C[mt][nt][0] * adr[nt * 2] + C[mt][nt][1] * adr[nt * 2 + 1];
            sb2 += C[mt][nt][2] * asr[nt * 2] + C[mt][nt][3] * asr[nt * 2 + 1];
            db  += C[mt][nt][2] * adr[nt * 2] + C[mt][nt][3] * adr[nt * 2 + 1];
        }
#pragma unroll
        for (int o = 1; o <= 2; o <<= 1) {
            sa  += __shfl_xor_sync(0xFFFFFFFFu, sa, o);
            da  += __shfl_xor_sync(0xFFFFFFFFu, da, o);
            sb2 += __shfl_xor_sync(0xFFFFFFFFu, sb2, o);
            db  += __shfl_xor_sync(0xFFFFFFFFu, db, o);
        }
        if (q == 0 && ra < N_NODES) { g_as1[ra * NH + head] = sa;  g_ad1[ra * NH + head] = da; }
        if (q == 0 && rb < N_NODES) { g_as1[rb * NH + head] = sb2; g_ad1[rb * NH + head] = db; }

#pragma unroll
        for (int nt = 0; nt < 4; nt++) {
            int col = head * 32 + nt * 8 + q * 2;
            if (ra < N_NODES)
                *(__half2*)(g_z1h + (size_t)ra * HC + col) =
                    __floats2half2_rn(C[mt][nt][0], C[mt][nt][1]);
            if (rb < N_NODES)
                *(__half2*)(g_z1h + (size_t)rb * HC + col) =
                    __floats2half2_rn(C[mt][nt][2], C[mt][nt][3]);
        }
    }
}

// ---------------- fused layer-1 GAT: single-pass softmax + aggregate ---------
// acc = sum(exp(l)*z); out = acc / sum(exp(l)) — numerator and denominator
// accumulated in ONE edge pass (normalizer applied at the end).
__global__ __launch_bounds__(256) void gat1_fused(const float* __restrict__ b1) {
    int lane = threadIdx.x & 31;
    int dst  = blockIdx.x * 8 + (threadIdx.x >> 5);
    if (dst >= N_NODES) return;
    int beg = g_rowptr[dst], end = g_rowptr[dst + 1];

    int   hme = lane >> 2;                 // head of my 8 channels
    float adm = g_ad1[dst * NH + hme];

    float smq = 0.f;
    float acc[8];
#pragma unroll
    for (int i = 0; i < 8; i++) acc[i] = 0.f;
#pragma unroll 8
    for (int j = beg; j < end; j++) {
        int s = g_csrc[j];
        float wt = __expf(lrelu(g_as1[s * NH + hme] + adm));
        smq += wt;
        uint4 zv = *((const uint4*)(g_z1h + (size_t)s * HC) + lane);
        float2 p0 = __half22float2(*(__half2*)&zv.x);
        float2 p1 = __half22float2(*(__half2*)&zv.y);
        float2 p2 = __half22float2(*(__half2*)&zv.z);
        float2 p3 = __half22float2(*(__half2*)&zv.w);
        acc[0] += wt * p0.x; acc[1] += wt * p0.y;
        acc[2] += wt * p1.x; acc[3] += wt * p1.y;
        acc[4] += wt * p2.x; acc[5] += wt * p2.y;
        acc[6] += wt * p3.x; acc[7] += wt * p3.y;
    }
    float inv = 1.f / smq;

    const float4* bb = (const float4*)(b1 + lane * 8);
    float4 bv0 = bb[0], bv1 = bb[1];
    float r[8] = {acc[0] * inv + bv0.x, acc[1] * inv + bv0.y,
                  acc[2] * inv + bv0.z, acc[3] * inv + bv0.w,
                  acc[4] * inv + bv1.x, acc[5] * inv + bv1.y,
                  acc[6] * inv + bv1.z, acc[7] * inv + bv1.w};
#pragma unroll
    for (int i = 0; i < 8; i++) r[i] = r[i] > 0.f ? r[i] : expm1f(r[i]);
    uint4 hv = make_uint4(pack_h2(r[0], r[1]), pack_h2(r[2], r[3]),
                          pack_h2(r[4], r[5]), pack_h2(r[6], r[7]));
    *(uint4*)(g_h1h + (size_t)dst * HC + lane * 8) = hv;
}

// ---------------- mma.sync GEMM2: z2 = h1h @ W2, fp16 A + split-fp16 B -------
// CTA: 256 thr (8 warps), tile 128(M) x 32(N); A via cp.async from fp16 h1.
// smem: BH 0..16K | BL 16K..32K | A-buf0 32K..40K | A-buf1 40K..48K
__global__ __launch_bounds__(256, 2) void mmagemm2(const float* __restrict__ a_src2,
                                                   const float* __restrict__ a_dst2) {
    extern __shared__ char sm2[];
    uint32_t base = smem_u32(sm2);

    int tid = threadIdx.x, lane = tid & 31, wid = tid >> 5;
    int row0 = blockIdx.x * 128;

    int r0s = tid >> 2,         c0s = (tid & 3) << 3;
    int r1s = (tid + 256) >> 2, c1s = (tid & 3) << 3;
    uint32_t swA0 = swz(r0s, c0s), swA1 = swz(r1s, c1s);

    // ---- stage B once: [32][256] fp16 hi/lo in 8 chunks of [32][32] ----
#pragma unroll
    for (int i = 0; i < 4; i++) {
        int f = tid + i * 256;
        int n = f >> 5, c8 = (f & 31) << 3;
        uint4 vh = *(const uint4*)(g_w2h + (size_t)n * N_FEAT + c8);
        uint4 vl = *(const uint4*)(g_w2l + (size_t)n * N_FEAT + c8);
        uint32_t so = (uint32_t)(c8 >> 5) * 2048 + swz(n, c8 & 31);
        *(uint4*)(sm2 + so)          = vh;
        *(uint4*)(sm2 + 16384 + so)  = vl;
    }

    float C[4][4];
#pragma unroll
    for (int nt = 0; nt < 4; nt++)
#pragma unroll
        for (int j = 0; j < 4; j++) C[nt][j] = 0.f;

    auto issueA = [&](int kt, uint32_t bufoff) {
#pragma unroll
        for (int i = 0; i < 2; i++) {
            int r = i ? r1s : r0s, c = i ? c1s : c0s;
            cp16(base + bufoff + (i ? swA1 : swA0),
                 g_h1h + (size_t)(row0 + r) * N_FEAT + kt * 32 + c);
        }
    };

    issueA(0, 32768);
    cp_commit();
    cp_wait0();
    __syncthreads();

    for (int kt = 0; kt < 8; kt++) {
        uint32_t cur = 32768 + (uint32_t)(kt & 1) * 8192;
        uint32_t nxt = 32768 + 8192 - (cur - 32768);
        if (kt < 7) {
            issueA(kt + 1, nxt);
            cp_commit();
        }

        uint32_t uA = base + cur;
        uint32_t bchunk = (uint32_t)kt * 2048;
#pragma unroll
        for (int ki = 0; ki < 2; ki++) {
            uint32_t Ah[4], Bh[4][2], Bl[4][2];
            int g = lane >> 3, lr = lane & 7;
            int arow = wid * 16 + (g & 1) * 8 + lr;
            int ak = ki * 16 + (g >> 1) * 8;
            ldsm_x4(Ah[0], Ah[1], Ah[2], Ah[3], uA + swz(arow, ak));

            int bn = lane & 7;
            int bk = ki * 16 + ((lane >> 3) & 1) * 8;
#pragma unroll
            for (int nt = 0; nt < 4; nt++) {
                uint32_t so = bchunk + swz(nt * 8 + bn, bk);
                ldsm_x2(Bh[nt][0], Bh[nt][1], base + so);
                ldsm_x2(Bl[nt][0], Bl[nt][1], base + 16384 + so);
            }
#pragma unroll
            for (int nt = 0; nt < 4; nt++) {
                mma16816h(C[nt], Ah, Bh[nt]);
                mma16816h(C[nt], Ah, Bl[nt]);
            }
        }
        if (kt < 7) cp_wait0();
        __syncthreads();
    }

    // ---- epilogue: z2(fp16) stores + fused alpha2 (rows cover all 32 cols) --
    int q = lane & 3, hrow = lane >> 2;
    float asr[8], adr[8];
#pragma unroll
    for (int nt = 0; nt < 4; nt++)
#pragma unroll
        for (int j = 0; j < 2; j++) {
            int col = nt * 8 + q * 2 + j;
            asr[nt * 2 + j] = __ldg(a_src2 + col);
            adr[nt * 2 + j] = __ldg(a_dst2 + col);
        }

    int ra = row0 + wid * 16 + hrow;
    int rb = ra + 8;
    float sa = 0.f, da = 0.f, sb2 = 0.f, db = 0.f;
#pragma unroll
    for (int nt = 0; nt < 4; nt++) {
        sa  += C[nt][0] * asr[nt * 2] + C[nt][1] * asr[nt * 2 + 1];
        da  += C[nt][0] * adr[nt * 2] + C[nt][1] * adr[nt * 2 + 1];
        sb2 += C[nt][2] * asr[nt * 2] + C[nt][3] * asr[nt * 2 + 1];
        db  += C[nt][2] * adr[nt * 2] + C[nt][3] * adr[nt * 2 + 1];
    }
#pragma unroll
    for (int o = 1; o <= 2; o <<= 1) {
        sa  += __shfl_xor_sync(0xFFFFFFFFu, sa, o);
        da  += __shfl_xor_sync(0xFFFFFFFFu, da, o);
        sb2 += __shfl_xor_sync(0xFFFFFFFFu, sb2, o);
        db  += __shfl_xor_sync(0xFFFFFFFFu, db, o);
    }
    if (q == 0 && ra < N_NODES) { g_as2[ra] = sa;  g_ad2[ra] = da; }
    if (q == 0 && rb < N_NODES) { g_as2[rb] = sb2; g_ad2[rb] = db; }

#pragma unroll
    for (int nt = 0; nt < 4; nt++) {
        int col = nt * 8 + q * 2;
        if (ra < N_NODES)
            *(__half2*)(g_z2h + (size_t)ra * NC + col) =
                __floats2half2_rn(C[nt][0], C[nt][1]);
        if (rb < N_NODES)
            *(__half2*)(g_z2h + (size_t)rb * NC + col) =
                __floats2half2_rn(C[nt][2], C[nt][3]);
    }
}

// ---------------- fused layer-2 GAT: single-pass softmax + bias -> out -------
__global__ __launch_bounds__(256) void gat2_fused(float* __restrict__ out,
                                                  const float* __restrict__ b2) {
    int lane = threadIdx.x & 31;
    int dst  = blockIdx.x * 8 + (threadIdx.x >> 5);
    if (dst >= N_NODES) return;
    int beg = g_rowptr[dst], end = g_rowptr[dst + 1];
    float adv = g_ad2[dst];

    float smv = 0.f, acc = 0.f;
#pragma unroll 8
    for (int j = beg; j < end; j++) {
        int s = g_csrc[j];
        float wt = __expf(lrelu(g_as2[s] + adv));
        smv += wt;
        acc += wt * __half2float(g_z2h[(size_t)s * NC + lane]);
    }
    out[(size_t)dst * NC + lane] = acc / smv + b2[lane];
}

// ---------------- launch ------------------------------------------------------
extern "C" void kernel_launch(void* const* d_in, const int* in_sizes, int n_in,
                              void* d_out, int out_size) {
    const float* x      = (const float*)d_in[0];
    const void*  ei     = d_in[1];
    const float* W1     = (const float*)d_in[2];
    const float* a_src1 = (const float*)d_in[3];
    const float* a_dst1 = (const float*)d_in[4];
    const float* b1     = (const float*)d_in[5];
    const float* W2     = (const float*)d_in[6];
    const float* a_src2 = (const float*)d_in[7];
    const float* a_dst2 = (const float*)d_in[8];
    const float* b2     = (const float*)d_in[9];
    float* out = (float*)d_out;

    const int T = 256;
    const int SM_BYTES = 49152;

    // one-time host-side resources (no device memory; identical captured
    // work on every call)
    static cudaStream_t s_side = nullptr;
    static cudaEvent_t  s_fork = nullptr, s_join = nullptr;
    if (s_side == nullptr) {
        cudaStreamCreateWithFlags(&s_side, cudaStreamNonBlocking);
        cudaEventCreateWithFlags(&s_fork, cudaEventDisableTiming);
        cudaEventCreateWithFlags(&s_join, cudaEventDisableTiming);
        cudaFuncSetAttribute(mmagemm1,
                             cudaFuncAttributeMaxDynamicSharedMemorySize, SM_BYTES);
        cudaFuncSetAttribute(mmagemm2,
                             cudaFuncAttributeMaxDynamicSharedMemorySize, SM_BYTES);
    }

    // main stream: prep -> (fork) -> mmagemm1 ... ; side stream: CSR build
    prep_kernel<<<(N_FEAT * HC + T - 1) / T, T>>>(W1, W2, ei);
    cudaEventRecord(s_fork, 0);
    cudaStreamWaitEvent(s_side, s_fork, 0);

    decode_kernel<<<(TOT_E + T - 1) / T, T, 0, s_side>>>(ei);
    scan1_kernel<<<NBLK, SCAN_B, 0, s_side>>>();
    {
        dim3 grid(2, (N_NODES + 127) / 128);
        mmagemm1<<<grid, 256, SM_BYTES>>>(x, a_src1, a_dst1);   // launch #4
    }
    scan2_kernel<<<1, 1, 0, s_side>>>();
    scan3_kernel<<<NBLK, SCAN_B, 0, s_side>>>();
    scatter_kernel<<<(TOT_E + T - 1) / T, T, 0, s_side>>>();
    cudaEventRecord(s_join, s_side);
    cudaStreamWaitEvent(0, s_join, 0);

    gat1_fused<<<(N_NODES + 7) / 8, 256>>>(b1);
    mmagemm2<<<(N_NODES + 127) / 128, 256, SM_BYTES>>>(a_src2, a_dst2);
    gat2_fused<<<(N_NODES + 7) / 8, 256>>>(out, b2);
}